// round 6
// baseline (speedup 1.0000x reference)
#include <cuda_runtime.h>
#include <math.h>
#include <stdint.h>

#define Nn 100000
#define Ee 1600000
#define DIN 128
#define Hh 256
#define Cc 47
#define Bb 16384
#define Kk 10

// ---------------- scratch (static device globals; allocation-free) ----------
__device__ float g_h0[(size_t)Nn * Hh];
__device__ float g_xc[(size_t)Nn * Hh];
__device__ float g_acc[(size_t)Nn * Hh];
__device__ float g_al[Nn], g_ar[Nn], g_dinv[Nn];
__device__ int   g_deg[Nn], g_fill[Nn], g_rowptr[Nn + 1];
__device__ int   g_src[Ee], g_dst[Ee];
__device__ float g_coef[Ee];
__device__ float g_an[(size_t)Bb * Hh];
__device__ float g_sim[(size_t)Bb * Bb];       // 1 GiB
__device__ float g_plc[Bb * Cc];
__device__ float g_topv[Bb * Kk];
__device__ int   g_topi[Bb * Kk];
__device__ int   g_is64;                        // 1 if edge_index/y are int64

// ---------------- dtype detection -------------------------------------------
// JAX under default (x64-disabled) config silently downcasts jnp.int64 to
// int32 — so edge_index/y may arrive as int32. Reading packed int32 pairs as
// int64 yields values >= 2^32 whenever the high word != 0, which random
// indices in [0,N) hit w.h.p. within 16 samples.
__global__ void k_detect(const void* ei) {
    const long long* p = (const long long*)ei;
    int ok64 = 1;
    for (int i = 0; i < 16; i++) {
        long long v = p[i];
        if (v < 0 || v >= (long long)Nn) ok64 = 0;
    }
    g_is64 = ok64;
}

__device__ __forceinline__ int load_idx(const void* buf, size_t i) {
    return g_is64 ? (int)((const long long*)buf)[i] : ((const int*)buf)[i];
}

// ---------------- graph preprocessing ---------------------------------------
__global__ void k_zero() {
    int i = blockIdx.x * blockDim.x + threadIdx.x;
    if (i < Nn) { g_deg[i] = 0; g_fill[i] = 0; }
}

__global__ void k_deg(const void* __restrict__ ei) {
    int e = blockIdx.x * blockDim.x + threadIdx.x;
    if (e < Ee) {
        int c = load_idx(ei, (size_t)Ee + e);
        if ((unsigned)c < (unsigned)Nn) atomicAdd(&g_deg[c], 1);
    }
}

// single-block serial-chunk scan: rowptr = exclusive prefix sum of deg
__global__ void k_scan() {
    __shared__ int s[1024];
    int t = threadIdx.x;
    int offset = 0;
    for (int base = 0; base < Nn; base += 1024) {
        int v = (base + t < Nn) ? g_deg[base + t] : 0;
        __syncthreads();           // protect previous chunk reads
        s[t] = v;
        __syncthreads();
        for (int d = 1; d < 1024; d <<= 1) {
            int u = (t >= d) ? s[t - d] : 0;
            __syncthreads();
            s[t] += u;
            __syncthreads();
        }
        if (base + t < Nn) g_rowptr[base + t + 1] = offset + s[t];
        offset += s[1023];
    }
    if (t == 0) g_rowptr[0] = 0;
}

__global__ void k_dinv() {
    int i = blockIdx.x * blockDim.x + threadIdx.x;
    if (i < Nn) {
        int d = g_deg[i];
        g_dinv[i] = (d > 0) ? rsqrtf((float)d) : 0.f;
    }
}

__global__ void k_fill(const void* __restrict__ ei) {
    int e = blockIdx.x * blockDim.x + threadIdx.x;
    if (e < Ee) {
        int r = load_idx(ei, e);
        int c = load_idx(ei, (size_t)Ee + e);
        if ((unsigned)r < (unsigned)Nn && (unsigned)c < (unsigned)Nn) {
            int pos = g_rowptr[c] + atomicAdd(&g_fill[c], 1);
            g_src[pos] = r;
            g_dst[pos] = c;
        }
    }
}

// ---------------- stage A: h0 = relu(x @ W1 + b1) ---------------------------
__global__ __launch_bounds__(256) void k_h0(const float* __restrict__ x,
                                            const float* __restrict__ W1,
                                            const float* __restrict__ b1) {
    __shared__ float xs[32][128];
    int row0 = blockIdx.x * 32;
    int t = threadIdx.x;
#pragma unroll
    for (int i = 0; i < 16; i++) {
        int el = t + i * 256;
        int r = el >> 7, k = el & 127;
        int gr = row0 + r;
        xs[r][k] = (gr < Nn) ? x[(size_t)gr * DIN + k] : 0.f;
    }
    __syncthreads();
    int c = t;
    float acc[32];
#pragma unroll
    for (int r = 0; r < 32; r++) acc[r] = 0.f;
    for (int k = 0; k < 128; k++) {
        float w = W1[k * Hh + c];
#pragma unroll
        for (int r = 0; r < 32; r++) acc[r] = fmaf(xs[r][k], w, acc[r]);
    }
    float bb = b1[c];
#pragma unroll
    for (int r = 0; r < 32; r++) {
        int gr = row0 + r;
        if (gr < Nn) g_h0[(size_t)gr * Hh + c] = fmaxf(acc[r] + bb, 0.f);
    }
}

// ---------------- per-layer: al/ar node dots ---------------------------------
__global__ void k_alar(int layer, const float* __restrict__ attl,
                       const float* __restrict__ attlb,
                       const float* __restrict__ attr,
                       const float* __restrict__ attrb) {
    __shared__ float wl[Hh], wr[Hh];
    int t = threadIdx.x;
    wl[t] = attl[layer * Hh + t];
    wr[t] = attr[layer * Hh + t];
    __syncthreads();
    int warp = t >> 5, lane = t & 31;
    int node = blockIdx.x * 8 + warp;
    if (node >= Nn) return;
    const float* xc = layer ? g_xc : g_h0;
    const float4* xr = (const float4*)(xc + (size_t)node * Hh);
    float4 a = xr[lane], b = xr[lane + 32];
    const float4* wl4 = (const float4*)wl;
    const float4* wr4 = (const float4*)wr;
    float4 l0 = wl4[lane], l1 = wl4[lane + 32];
    float4 r0 = wr4[lane], r1 = wr4[lane + 32];
    float sl = a.x*l0.x + a.y*l0.y + a.z*l0.z + a.w*l0.w
             + b.x*l1.x + b.y*l1.y + b.z*l1.z + b.w*l1.w;
    float sr = a.x*r0.x + a.y*r0.y + a.z*r0.z + a.w*r0.w
             + b.x*r1.x + b.y*r1.y + b.z*r1.z + b.w*r1.w;
#pragma unroll
    for (int o = 16; o; o >>= 1) {
        sl += __shfl_down_sync(0xffffffffu, sl, o);
        sr += __shfl_down_sync(0xffffffffu, sr, o);
    }
    if (lane == 0) {
        g_al[node] = sl + attlb[layer];
        g_ar[node] = sr + attrb[layer];
    }
}

// ---------------- per-layer: per-edge coefficient ---------------------------
__global__ void k_coef() {
    int p = blockIdx.x * blockDim.x + threadIdx.x;
    if (p < Ee) {
        int r = g_src[p], c = g_dst[p];
        g_coef[p] = tanhf(g_al[r] + g_ar[c]) * g_dinv[r] * g_dinv[c];
    }
}

// ---------------- per-layer: gather (segment_sum by col) --------------------
__device__ __forceinline__ void fma4(float4& acc, const float4 u, const float s) {
    acc.x = fmaf(u.x, s, acc.x);
    acc.y = fmaf(u.y, s, acc.y);
    acc.z = fmaf(u.z, s, acc.z);
    acc.w = fmaf(u.w, s, acc.w);
}

__global__ void k_gather(int layer) {
    int gw = (blockIdx.x * blockDim.x + threadIdx.x) >> 5;
    int lane = threadIdx.x & 31;
    if (gw >= Nn) return;
    const float* xc = layer ? g_xc : g_h0;
    int s = g_rowptr[gw], e = g_rowptr[gw + 1];
    float4 a0 = make_float4(0.f, 0.f, 0.f, 0.f), a1 = a0;
    int p = s;
    for (; p + 2 <= e; p += 2) {
        int r0 = g_src[p], r1 = g_src[p + 1];
        float w0 = g_coef[p], w1 = g_coef[p + 1];
        const float4* x0 = (const float4*)(xc + (size_t)r0 * Hh);
        const float4* x1 = (const float4*)(xc + (size_t)r1 * Hh);
        float4 u0 = x0[lane], v0 = x0[lane + 32];
        float4 u1 = x1[lane], v1 = x1[lane + 32];
        fma4(a0, u0, w0); fma4(a1, v0, w0);
        fma4(a0, u1, w1); fma4(a1, v1, w1);
    }
    if (p < e) {
        int r0 = g_src[p];
        float w0 = g_coef[p];
        const float4* x0 = (const float4*)(xc + (size_t)r0 * Hh);
        float4 u0 = x0[lane], v0 = x0[lane + 32];
        fma4(a0, u0, w0); fma4(a1, v0, w0);
    }
    float4* o = (float4*)(g_acc + (size_t)gw * Hh);
    o[lane] = a0;
    o[lane + 32] = a1;
}

// ---------------- per-layer: xc = relu(acc + 0.3*h0) ------------------------
__global__ void k_finalize() {
    size_t i = (size_t)blockIdx.x * blockDim.x + threadIdx.x;  // over N*H/4
    const float4 a = ((const float4*)g_acc)[i];
    const float4 h = ((const float4*)g_h0)[i];
    float4 r;
    r.x = fmaxf(fmaf(0.3f, h.x, a.x), 0.f);
    r.y = fmaxf(fmaf(0.3f, h.y, a.y), 0.f);
    r.z = fmaxf(fmaf(0.3f, h.z, a.z), 0.f);
    r.w = fmaxf(fmaf(0.3f, h.w, a.w), 0.f);
    ((float4*)g_xc)[i] = r;
}

// ---------------- normalize + emit embedding --------------------------------
__global__ void k_an(float* __restrict__ emb, int write_emb) {
    int t = threadIdx.x, warp = t >> 5, lane = t & 31;
    int b = blockIdx.x * 8 + warp;
    if (b >= Bb) return;
    const float4* xr = (const float4*)(g_xc + (size_t)b * Hh);
    float4 a = xr[lane], c = xr[lane + 32];
    float ss = a.x*a.x + a.y*a.y + a.z*a.z + a.w*a.w
             + c.x*c.x + c.y*c.y + c.z*c.z + c.w*c.w;
#pragma unroll
    for (int o = 16; o; o >>= 1) ss += __shfl_xor_sync(0xffffffffu, ss, o);
    float inv = 1.f / fmaxf(sqrtf(ss), 1e-8f);
    float4* anr = (float4*)(g_an + (size_t)b * Hh);
    float4 na = make_float4(a.x*inv, a.y*inv, a.z*inv, a.w*inv);
    float4 nc = make_float4(c.x*inv, c.y*inv, c.z*inv, c.w*inv);
    anr[lane] = na; anr[lane + 32] = nc;
    if (write_emb) {
        float4* er = (float4*)(emb + (size_t)b * Hh);
        er[lane] = a; er[lane + 32] = c;
    }
}

// ---------------- logits + log_softmax -> g_plc -----------------------------
__global__ void k_logits(const float* __restrict__ W2, const float* __restrict__ b2) {
    __shared__ float xs[8][256];
    int t = threadIdx.x, warp = t >> 5, lane = t & 31;
    int b = blockIdx.x * 8 + warp;
    if (b >= Bb) return;
    float4* xsw = (float4*)xs[warp];
    const float4* xr = (const float4*)(g_xc + (size_t)b * Hh);
    xsw[lane] = xr[lane];
    xsw[lane + 32] = xr[lane + 32];
    __syncwarp();
    int c0 = lane;
    int c1 = (lane < 15) ? lane + 32 : 0;
    float s0 = b2[c0], s1 = b2[c1];
    for (int k = 0; k < 256; k++) {
        float xv = xs[warp][k];
        s0 = fmaf(xv, W2[k * Cc + c0], s0);
        s1 = fmaf(xv, W2[k * Cc + c1], s1);
    }
    if (lane >= 15) s1 = -1e30f;
    float m = fmaxf(s0, s1);
#pragma unroll
    for (int o = 16; o; o >>= 1) m = fmaxf(m, __shfl_xor_sync(0xffffffffu, m, o));
    float se = expf(s0 - m) + ((lane < 15) ? expf(s1 - m) : 0.f);
#pragma unroll
    for (int o = 16; o; o >>= 1) se += __shfl_xor_sync(0xffffffffu, se, o);
    float lse = m + logf(se);
    g_plc[b * Cc + c0] = s0 - lse;
    if (lane < 15) g_plc[b * Cc + lane + 32] = s1 - lse;
}

// ---------------- sim = an @ an^T (symmetric, 64x64 tiles) ------------------
__global__ __launch_bounds__(256) void k_sim() {
    int bx = blockIdx.x, by = blockIdx.y;
    if (bx < by) return;
    __shared__ float As[16][72];
    __shared__ float Bs[16][72];
    __shared__ float Cs[64][68];
    int t = threadIdx.x;
    int tx = t & 15, ty = t >> 4;
    float acc[4][4];
#pragma unroll
    for (int i = 0; i < 4; i++)
#pragma unroll
        for (int j = 0; j < 4; j++) acc[i][j] = 0.f;

    const float* A = g_an + (size_t)(by * 64) * Hh;
    const float* Bm = g_an + (size_t)(bx * 64) * Hh;

    for (int kk = 0; kk < 256; kk += 16) {
#pragma unroll
        for (int i = 0; i < 4; i++) {
            int el = t + i * 256;
            int r = el >> 4, k = el & 15;
            As[k][r] = A[(size_t)r * Hh + kk + k];
            Bs[k][r] = Bm[(size_t)r * Hh + kk + k];
        }
        __syncthreads();
#pragma unroll
        for (int k = 0; k < 16; k++) {
            float4 av = *(const float4*)&As[k][ty * 4];
            float4 bv = *(const float4*)&Bs[k][tx * 4];
            acc[0][0] = fmaf(av.x, bv.x, acc[0][0]);
            acc[0][1] = fmaf(av.x, bv.y, acc[0][1]);
            acc[0][2] = fmaf(av.x, bv.z, acc[0][2]);
            acc[0][3] = fmaf(av.x, bv.w, acc[0][3]);
            acc[1][0] = fmaf(av.y, bv.x, acc[1][0]);
            acc[1][1] = fmaf(av.y, bv.y, acc[1][1]);
            acc[1][2] = fmaf(av.y, bv.z, acc[1][2]);
            acc[1][3] = fmaf(av.y, bv.w, acc[1][3]);
            acc[2][0] = fmaf(av.z, bv.x, acc[2][0]);
            acc[2][1] = fmaf(av.z, bv.y, acc[2][1]);
            acc[2][2] = fmaf(av.z, bv.z, acc[2][2]);
            acc[2][3] = fmaf(av.z, bv.w, acc[2][3]);
            acc[3][0] = fmaf(av.w, bv.x, acc[3][0]);
            acc[3][1] = fmaf(av.w, bv.y, acc[3][1]);
            acc[3][2] = fmaf(av.w, bv.z, acc[3][2]);
            acc[3][3] = fmaf(av.w, bv.w, acc[3][3]);
        }
        __syncthreads();
    }

    // normal tile (rows by, cols bx), coalesced float4 stores
#pragma unroll
    for (int i = 0; i < 4; i++) {
        float4 v = make_float4(acc[i][0], acc[i][1], acc[i][2], acc[i][3]);
        int r = by * 64 + ty * 4 + i;
        int cb = bx * 64 + tx * 4;
        *(float4*)&g_sim[(size_t)r * Bb + cb] = v;
    }

    if (bx != by) {
        // transposed tile via smem staging
#pragma unroll
        for (int i = 0; i < 4; i++)
#pragma unroll
            for (int j = 0; j < 4; j++)
                Cs[tx * 4 + j][ty * 4 + i] = acc[i][j];
        __syncthreads();
        int cl = t >> 2;          // 0..63 (transposed row = original col)
        int r0 = (t & 3) * 4;     // 0,4,8,12
        size_t obase = (size_t)(bx * 64 + cl) * Bb + by * 64 + r0;
#pragma unroll
        for (int m = 0; m < 4; m++) {
            float4 v = *(const float4*)&Cs[cl][r0 + m * 16];
            *(float4*)&g_sim[obase + (size_t)m * 16] = v;
        }
    }
}

// ---------------- top-k per row ----------------------------------------------
__global__ void k_topk() {
    __shared__ float sv[2560];
    __shared__ int   si[2560];
    __shared__ float rv[256];
    __shared__ int   ri[256];
    int b = blockIdx.x;
    int t = threadIdx.x;
    const float* srow = g_sim + (size_t)b * Bb;
    float v[10];
    int id[10];
#pragma unroll
    for (int i = 0; i < 10; i++) { v[i] = -1e30f; id[i] = 0; }
    for (int j = t; j < Bb; j += 256) {
        float s = srow[j];
        if (s > v[9]) {
            v[9] = s; id[9] = j;
#pragma unroll
            for (int i = 9; i > 0; i--) {
                if (v[i] > v[i - 1]) {
                    float tv = v[i]; v[i] = v[i - 1]; v[i - 1] = tv;
                    int ti = id[i]; id[i] = id[i - 1]; id[i - 1] = ti;
                }
            }
        }
    }
#pragma unroll
    for (int i = 0; i < 10; i++) { sv[t * 10 + i] = v[i]; si[t * 10 + i] = id[i]; }
    __syncthreads();
    for (int k = 0; k < 10; k++) {
        float bm = -1e30f; int bp = t * 10;
#pragma unroll
        for (int i = 0; i < 10; i++) {
            float x = sv[t * 10 + i];
            if (x > bm) { bm = x; bp = t * 10 + i; }
        }
        rv[t] = bm; ri[t] = bp;
        __syncthreads();
        for (int s = 128; s > 0; s >>= 1) {
            if (t < s) {
                if (rv[t + s] > rv[t]) { rv[t] = rv[t + s]; ri[t] = ri[t + s]; }
            }
            __syncthreads();
        }
        if (t == 0) {
            g_topv[b * Kk + k] = rv[0];
            g_topi[b * Kk + k] = si[ri[0]];
            sv[ri[0]] = -1e30f;
        }
        __syncthreads();
    }
}

// ---------------- fuse labels + p_sim + combine -----------------------------
__global__ void k_final(const void* __restrict__ y, float* __restrict__ out) {
    __shared__ float fu[8][48];
    int t = threadIdx.x, warp = t >> 5, lane = t & 31;
    int b = blockIdx.x * 8 + warp;
    if (b >= Bb) return;
    fu[warp][lane] = 0.f;
    if (lane < 16) fu[warp][lane + 32] = 0.f;
    __syncwarp();
    if (lane < Kk) {
        float val = g_topv[b * Kk + lane];
        int id = g_topi[b * Kk + lane];
        int cls = load_idx(y, id);
        if ((unsigned)cls < (unsigned)Cc)
            atomicAdd(&fu[warp][cls], expf(val));
    }
    __syncwarp();
    float f0 = fu[warp][lane];                       // c = lane (0..31)
    float f1 = (lane < 15) ? fu[warp][lane + 32] : -1e30f;
    float m = fmaxf(f0, f1);
#pragma unroll
    for (int o = 16; o; o >>= 1) m = fmaxf(m, __shfl_xor_sync(0xffffffffu, m, o));
    float se = expf(f0 - m) + ((lane < 15) ? expf(f1 - m) : 0.f);
#pragma unroll
    for (int o = 16; o; o >>= 1) se += __shfl_xor_sync(0xffffffffu, se, o);
    float lse = m + logf(se);
    out[b * Cc + lane] = 0.5f * g_plc[b * Cc + lane] + 0.5f * (f0 - lse);
    if (lane < 15)
        out[b * Cc + lane + 32] = 0.5f * g_plc[b * Cc + lane + 32] + 0.5f * (f1 - lse);
}

// ---------------- launcher ----------------------------------------------------
extern "C" void kernel_launch(void* const* d_in, const int* in_sizes, int n_in,
                              void* d_out, int out_size) {
    int i = 0;
    const float* x    = (const float*)d_in[i++];      // [N,128]
    const void*  ei   = d_in[i++];                    // [2,E] int32 or int64
    const void*  y    = d_in[i++];                    // [B]   int32 or int64
    if (i < n_in && in_sizes[i] == 1) i++;            // batch_size scalar (skip)
    const float* W1   = (const float*)d_in[i++];
    const float* b1   = (const float*)d_in[i++];
    const float* W2   = (const float*)d_in[i++];
    const float* b2   = (const float*)d_in[i++];
    const float* attl = (const float*)d_in[i++];
    const float* attlb= (const float*)d_in[i++];
    const float* attr = (const float*)d_in[i++];
    const float* attrb= (const float*)d_in[i++];
    float* out = (float*)d_out;

    // dtype probe, then graph structure (per launch; deterministic inputs)
    k_detect<<<1, 1>>>(ei);
    k_zero<<<(Nn + 255) / 256, 256>>>();
    k_deg<<<(Ee + 255) / 256, 256>>>(ei);
    k_scan<<<1, 1024>>>();
    k_dinv<<<(Nn + 255) / 256, 256>>>();
    k_fill<<<(Ee + 255) / 256, 256>>>(ei);

    // encoder
    k_h0<<<Nn / 32, 256>>>(x, W1, b1);
    for (int l = 0; l < 2; l++) {
        k_alar<<<Nn / 8, 256>>>(l, attl, attlb, attr, attrb);
        k_coef<<<(Ee + 255) / 256, 256>>>();
        k_gather<<<Nn / 8, 256>>>(l);
        k_finalize<<<(Nn * (Hh / 4)) / 256, 256>>>();
    }

    // head
    int write_emb = (out_size >= Bb * Cc + Bb * Hh) ? 1 : 0;
    k_an<<<Bb / 8, 256>>>(out + (size_t)Bb * Cc, write_emb);
    k_logits<<<Bb / 8, 256>>>(W2, b2);
    dim3 gs(Bb / 64, Bb / 64);
    k_sim<<<gs, 256>>>();
    k_topk<<<Bb, 256>>>();
    k_final<<<Bb / 8, 256>>>(y, out);
}

// round 7
// speedup vs baseline: 1.3081x; 1.3081x over previous
#include <cuda_runtime.h>
#include <math.h>
#include <stdint.h>

#define Nn 100000
#define Ee 1600000
#define DIN 128
#define Hh 256
#define Cc 47
#define Bb 16384
#define Kk 10
#define NBLK 98   // ceil(Nn/1024)

// ---------------- scratch (static device globals; allocation-free) ----------
__device__ float g_h0[(size_t)Nn * Hh];
__device__ float g_xc[(size_t)Nn * Hh];
__device__ float g_acc[(size_t)Nn * Hh];
__device__ float g_al[Nn], g_ar[Nn], g_dinv[Nn];
__device__ int   g_deg[Nn], g_fill[Nn], g_rowptr[Nn + 1];
__device__ int   g_bsum[128];
__device__ int   g_src[Ee], g_dst[Ee];
__device__ float g_coef[Ee];
__device__ float g_an[(size_t)Bb * Hh];
__device__ float g_sim[(size_t)Bb * Bb];       // 1 GiB
__device__ float g_plc[Bb * Cc];
__device__ float g_topv[Bb * Kk];
__device__ int   g_topi[Bb * Kk];
__device__ int   g_is64;                        // 1 if edge_index/y are int64

// ---------------- dtype detection -------------------------------------------
__global__ void k_detect(const void* ei) {
    const long long* p = (const long long*)ei;
    int ok64 = 1;
    for (int i = 0; i < 16; i++) {
        long long v = p[i];
        if (v < 0 || v >= (long long)Nn) ok64 = 0;
    }
    g_is64 = ok64;
}

__device__ __forceinline__ int load_idx(const void* buf, size_t i) {
    return g_is64 ? (int)((const long long*)buf)[i] : ((const int*)buf)[i];
}

// ---------------- graph preprocessing ---------------------------------------
__global__ void k_zero() {
    int i = blockIdx.x * blockDim.x + threadIdx.x;
    if (i < Nn) { g_deg[i] = 0; g_fill[i] = 0; }
}

__global__ void k_deg(const void* __restrict__ ei) {
    int e = blockIdx.x * blockDim.x + threadIdx.x;
    if (e < Ee) {
        int c = load_idx(ei, (size_t)Ee + e);
        if ((unsigned)c < (unsigned)Nn) atomicAdd(&g_deg[c], 1);
    }
}

// parallel scan: per-block inclusive scan + block sums
__global__ void k_scan1() {
    __shared__ int s[1024];
    int b = blockIdx.x, t = threadIdx.x;
    int i = b * 1024 + t;
    s[t] = (i < Nn) ? g_deg[i] : 0;
    __syncthreads();
    for (int d = 1; d < 1024; d <<= 1) {
        int u = (t >= d) ? s[t - d] : 0;
        __syncthreads();
        s[t] += u;
        __syncthreads();
    }
    if (i < Nn) g_rowptr[i + 1] = s[t];
    if (t == 1023) g_bsum[b] = s[t];
}

__global__ void k_scan2() {   // 1 block, 128 threads: inclusive scan of block sums
    __shared__ int s[128];
    int t = threadIdx.x;
    s[t] = (t < NBLK) ? g_bsum[t] : 0;
    __syncthreads();
    for (int d = 1; d < 128; d <<= 1) {
        int u = (t >= d) ? s[t - d] : 0;
        __syncthreads();
        s[t] += u;
        __syncthreads();
    }
    g_bsum[t] = s[t];
}

__global__ void k_scan3() {
    int i = blockIdx.x * blockDim.x + threadIdx.x;
    if (i < Nn) {
        int b = i / 1024;
        if (b > 0) g_rowptr[i + 1] += g_bsum[b - 1];
    }
    if (i == 0) g_rowptr[0] = 0;
}

__global__ void k_dinv() {
    int i = blockIdx.x * blockDim.x + threadIdx.x;
    if (i < Nn) {
        int d = g_deg[i];
        g_dinv[i] = (d > 0) ? rsqrtf((float)d) : 0.f;
    }
}

__global__ void k_fill(const void* __restrict__ ei) {
    int e = blockIdx.x * blockDim.x + threadIdx.x;
    if (e < Ee) {
        int r = load_idx(ei, e);
        int c = load_idx(ei, (size_t)Ee + e);
        if ((unsigned)r < (unsigned)Nn && (unsigned)c < (unsigned)Nn) {
            int pos = g_rowptr[c] + atomicAdd(&g_fill[c], 1);
            g_src[pos] = r;
            g_dst[pos] = c;
        }
    }
}

// ---------------- stage A: h0 = relu(x @ W1 + b1) ---------------------------
__global__ __launch_bounds__(256) void k_h0(const float* __restrict__ x,
                                            const float* __restrict__ W1,
                                            const float* __restrict__ b1) {
    __shared__ float xs[32][128];
    int row0 = blockIdx.x * 32;
    int t = threadIdx.x;
#pragma unroll
    for (int i = 0; i < 16; i++) {
        int el = t + i * 256;
        int r = el >> 7, k = el & 127;
        int gr = row0 + r;
        xs[r][k] = (gr < Nn) ? x[(size_t)gr * DIN + k] : 0.f;
    }
    __syncthreads();
    int c = t;
    float acc[32];
#pragma unroll
    for (int r = 0; r < 32; r++) acc[r] = 0.f;
    for (int k = 0; k < 128; k++) {
        float w = W1[k * Hh + c];
#pragma unroll
        for (int r = 0; r < 32; r++) acc[r] = fmaf(xs[r][k], w, acc[r]);
    }
    float bb = b1[c];
#pragma unroll
    for (int r = 0; r < 32; r++) {
        int gr = row0 + r;
        if (gr < Nn) g_h0[(size_t)gr * Hh + c] = fmaxf(acc[r] + bb, 0.f);
    }
}

// ---------------- per-layer: al/ar node dots ---------------------------------
__global__ void k_alar(int layer, const float* __restrict__ attl,
                       const float* __restrict__ attlb,
                       const float* __restrict__ attr,
                       const float* __restrict__ attrb) {
    __shared__ float wl[Hh], wr[Hh];
    int t = threadIdx.x;
    wl[t] = attl[layer * Hh + t];
    wr[t] = attr[layer * Hh + t];
    __syncthreads();
    int warp = t >> 5, lane = t & 31;
    int node = blockIdx.x * 8 + warp;
    if (node >= Nn) return;
    const float* xc = layer ? g_xc : g_h0;
    const float4* xr = (const float4*)(xc + (size_t)node * Hh);
    float4 a = xr[lane], b = xr[lane + 32];
    const float4* wl4 = (const float4*)wl;
    const float4* wr4 = (const float4*)wr;
    float4 l0 = wl4[lane], l1 = wl4[lane + 32];
    float4 r0 = wr4[lane], r1 = wr4[lane + 32];
    float sl = a.x*l0.x + a.y*l0.y + a.z*l0.z + a.w*l0.w
             + b.x*l1.x + b.y*l1.y + b.z*l1.z + b.w*l1.w;
    float sr = a.x*r0.x + a.y*r0.y + a.z*r0.z + a.w*r0.w
             + b.x*r1.x + b.y*r1.y + b.z*r1.z + b.w*r1.w;
#pragma unroll
    for (int o = 16; o; o >>= 1) {
        sl += __shfl_down_sync(0xffffffffu, sl, o);
        sr += __shfl_down_sync(0xffffffffu, sr, o);
    }
    if (lane == 0) {
        g_al[node] = sl + attlb[layer];
        g_ar[node] = sr + attrb[layer];
    }
}

// ---------------- per-layer: per-edge coefficient ---------------------------
// limit_nodes: only edges with dst < limit_nodes are needed downstream.
__global__ void k_coef(int limit_nodes) {
    int p = blockIdx.x * blockDim.x + threadIdx.x;
    int bound = g_rowptr[limit_nodes];    // CSR sorted by dst
    if (p < bound) {
        int r = g_src[p], c = g_dst[p];
        g_coef[p] = tanhf(g_al[r] + g_ar[c]) * g_dinv[r] * g_dinv[c];
    }
}

// ---------------- per-layer: gather (segment_sum by col) --------------------
__device__ __forceinline__ void fma4(float4& acc, const float4 u, const float s) {
    acc.x = fmaf(u.x, s, acc.x);
    acc.y = fmaf(u.y, s, acc.y);
    acc.z = fmaf(u.z, s, acc.z);
    acc.w = fmaf(u.w, s, acc.w);
}

__global__ void k_gather(int layer, int nodes) {
    int gw = (blockIdx.x * blockDim.x + threadIdx.x) >> 5;
    int lane = threadIdx.x & 31;
    if (gw >= nodes) return;
    const float* xc = layer ? g_xc : g_h0;
    int s = g_rowptr[gw], e = g_rowptr[gw + 1];
    float4 a0 = make_float4(0.f, 0.f, 0.f, 0.f), a1 = a0;
    int p = s;
    for (; p + 2 <= e; p += 2) {
        int r0 = g_src[p], r1 = g_src[p + 1];
        float w0 = g_coef[p], w1 = g_coef[p + 1];
        const float4* x0 = (const float4*)(xc + (size_t)r0 * Hh);
        const float4* x1 = (const float4*)(xc + (size_t)r1 * Hh);
        float4 u0 = x0[lane], v0 = x0[lane + 32];
        float4 u1 = x1[lane], v1 = x1[lane + 32];
        fma4(a0, u0, w0); fma4(a1, v0, w0);
        fma4(a0, u1, w1); fma4(a1, v1, w1);
    }
    if (p < e) {
        int r0 = g_src[p];
        float w0 = g_coef[p];
        const float4* x0 = (const float4*)(xc + (size_t)r0 * Hh);
        float4 u0 = x0[lane], v0 = x0[lane + 32];
        fma4(a0, u0, w0); fma4(a1, v0, w0);
    }
    float4* o = (float4*)(g_acc + (size_t)gw * Hh);
    o[lane] = a0;
    o[lane + 32] = a1;
}

// ---------------- per-layer: xc = relu(acc + 0.3*h0) ------------------------
__global__ void k_finalize() {
    size_t i = (size_t)blockIdx.x * blockDim.x + threadIdx.x;  // over rows*H/4
    const float4 a = ((const float4*)g_acc)[i];
    const float4 h = ((const float4*)g_h0)[i];
    float4 r;
    r.x = fmaxf(fmaf(0.3f, h.x, a.x), 0.f);
    r.y = fmaxf(fmaf(0.3f, h.y, a.y), 0.f);
    r.z = fmaxf(fmaf(0.3f, h.z, a.z), 0.f);
    r.w = fmaxf(fmaf(0.3f, h.w, a.w), 0.f);
    ((float4*)g_xc)[i] = r;
}

// ---------------- normalize + emit embedding --------------------------------
__global__ void k_an(float* __restrict__ emb, int write_emb) {
    int t = threadIdx.x, warp = t >> 5, lane = t & 31;
    int b = blockIdx.x * 8 + warp;
    if (b >= Bb) return;
    const float4* xr = (const float4*)(g_xc + (size_t)b * Hh);
    float4 a = xr[lane], c = xr[lane + 32];
    float ss = a.x*a.x + a.y*a.y + a.z*a.z + a.w*a.w
             + c.x*c.x + c.y*c.y + c.z*c.z + c.w*c.w;
#pragma unroll
    for (int o = 16; o; o >>= 1) ss += __shfl_xor_sync(0xffffffffu, ss, o);
    float inv = 1.f / fmaxf(sqrtf(ss), 1e-8f);
    float4* anr = (float4*)(g_an + (size_t)b * Hh);
    float4 na = make_float4(a.x*inv, a.y*inv, a.z*inv, a.w*inv);
    float4 nc = make_float4(c.x*inv, c.y*inv, c.z*inv, c.w*inv);
    anr[lane] = na; anr[lane + 32] = nc;
    if (write_emb) {
        float4* er = (float4*)(emb + (size_t)b * Hh);
        er[lane] = a; er[lane + 32] = c;
    }
}

// ---------------- logits + log_softmax -> g_plc -----------------------------
__global__ void k_logits(const float* __restrict__ W2, const float* __restrict__ b2) {
    __shared__ float xs[8][256];
    int t = threadIdx.x, warp = t >> 5, lane = t & 31;
    int b = blockIdx.x * 8 + warp;
    if (b >= Bb) return;
    float4* xsw = (float4*)xs[warp];
    const float4* xr = (const float4*)(g_xc + (size_t)b * Hh);
    xsw[lane] = xr[lane];
    xsw[lane + 32] = xr[lane + 32];
    __syncwarp();
    int c0 = lane;
    int c1 = (lane < 15) ? lane + 32 : 0;
    float s0 = b2[c0], s1 = b2[c1];
    for (int k = 0; k < 256; k++) {
        float xv = xs[warp][k];
        s0 = fmaf(xv, W2[k * Cc + c0], s0);
        s1 = fmaf(xv, W2[k * Cc + c1], s1);
    }
    if (lane >= 15) s1 = -1e30f;
    float m = fmaxf(s0, s1);
#pragma unroll
    for (int o = 16; o; o >>= 1) m = fmaxf(m, __shfl_xor_sync(0xffffffffu, m, o));
    float se = expf(s0 - m) + ((lane < 15) ? expf(s1 - m) : 0.f);
#pragma unroll
    for (int o = 16; o; o >>= 1) se += __shfl_xor_sync(0xffffffffu, se, o);
    float lse = m + logf(se);
    g_plc[b * Cc + c0] = s0 - lse;
    if (lane < 15) g_plc[b * Cc + lane + 32] = s1 - lse;
}

// ---------------- sim = an @ an^T (symmetric, 128x128 tiles, 8x8/thr) -------
__global__ __launch_bounds__(256, 2) void k_sim() {
    int bx = blockIdx.x, by = blockIdx.y;
    if (bx < by) return;
    __shared__ float As[16][132];
    __shared__ float Bs[16][132];
    int t = threadIdx.x;
    int tx = t & 15, ty = t >> 4;
    float acc[8][8];
#pragma unroll
    for (int i = 0; i < 8; i++)
#pragma unroll
        for (int j = 0; j < 8; j++) acc[i][j] = 0.f;

    const float* A = g_an + (size_t)(by * 128) * Hh;
    const float* B = g_an + (size_t)(bx * 128) * Hh;

    for (int kk = 0; kk < Hh; kk += 16) {
#pragma unroll
        for (int i = 0; i < 2; i++) {
            int idx = t + i * 256;        // 0..511
            int r = idx >> 2;             // row 0..127
            int kq = (idx & 3) * 4;       // k-offset 0,4,8,12
            float4 va = *(const float4*)(A + (size_t)r * Hh + kk + kq);
            As[kq + 0][r] = va.x; As[kq + 1][r] = va.y;
            As[kq + 2][r] = va.z; As[kq + 3][r] = va.w;
            float4 vb = *(const float4*)(B + (size_t)r * Hh + kk + kq);
            Bs[kq + 0][r] = vb.x; Bs[kq + 1][r] = vb.y;
            Bs[kq + 2][r] = vb.z; Bs[kq + 3][r] = vb.w;
        }
        __syncthreads();
#pragma unroll
        for (int k = 0; k < 16; k++) {
            float a[8], b[8];
            *(float4*)(a)     = *(const float4*)&As[k][ty * 8];
            *(float4*)(a + 4) = *(const float4*)&As[k][ty * 8 + 4];
            *(float4*)(b)     = *(const float4*)&Bs[k][tx * 8];
            *(float4*)(b + 4) = *(const float4*)&Bs[k][tx * 8 + 4];
#pragma unroll
            for (int i = 0; i < 8; i++)
#pragma unroll
                for (int j = 0; j < 8; j++)
                    acc[i][j] = fmaf(a[i], b[j], acc[i][j]);
        }
        __syncthreads();
    }

    int r0 = by * 128 + ty * 8;
    int c0 = bx * 128 + tx * 8;
#pragma unroll
    for (int i = 0; i < 8; i++) {
        float4 v0 = make_float4(acc[i][0], acc[i][1], acc[i][2], acc[i][3]);
        float4 v1 = make_float4(acc[i][4], acc[i][5], acc[i][6], acc[i][7]);
        *(float4*)&g_sim[(size_t)(r0 + i) * Bb + c0]     = v0;
        *(float4*)&g_sim[(size_t)(r0 + i) * Bb + c0 + 4] = v1;
    }
    if (bx != by) {
#pragma unroll
        for (int j = 0; j < 8; j++) {
            float4 v0 = make_float4(acc[0][j], acc[1][j], acc[2][j], acc[3][j]);
            float4 v1 = make_float4(acc[4][j], acc[5][j], acc[6][j], acc[7][j]);
            *(float4*)&g_sim[(size_t)(c0 + j) * Bb + r0]     = v0;
            *(float4*)&g_sim[(size_t)(c0 + j) * Bb + r0 + 4] = v1;
        }
    }
}

// ---------------- top-k per row ----------------------------------------------
__global__ void k_topk() {
    __shared__ float sv[2560];
    __shared__ int   si[2560];
    __shared__ float rv[256];
    __shared__ int   ri[256];
    int b = blockIdx.x;
    int t = threadIdx.x;
    const float* srow = g_sim + (size_t)b * Bb;
    float v[10];
    int id[10];
#pragma unroll
    for (int i = 0; i < 10; i++) { v[i] = -1e30f; id[i] = 0; }
    for (int j = t; j < Bb; j += 256) {
        float s = srow[j];
        if (s > v[9]) {
            v[9] = s; id[9] = j;
#pragma unroll
            for (int i = 9; i > 0; i--) {
                if (v[i] > v[i - 1]) {
                    float tv = v[i]; v[i] = v[i - 1]; v[i - 1] = tv;
                    int ti = id[i]; id[i] = id[i - 1]; id[i - 1] = ti;
                }
            }
        }
    }
#pragma unroll
    for (int i = 0; i < 10; i++) { sv[t * 10 + i] = v[i]; si[t * 10 + i] = id[i]; }
    __syncthreads();
    for (int k = 0; k < 10; k++) {
        float bm = -1e30f; int bp = t * 10;
#pragma unroll
        for (int i = 0; i < 10; i++) {
            float x = sv[t * 10 + i];
            if (x > bm) { bm = x; bp = t * 10 + i; }
        }
        rv[t] = bm; ri[t] = bp;
        __syncthreads();
        for (int s = 128; s > 0; s >>= 1) {
            if (t < s) {
                if (rv[t + s] > rv[t]) { rv[t] = rv[t + s]; ri[t] = ri[t + s]; }
            }
            __syncthreads();
        }
        if (t == 0) {
            g_topv[b * Kk + k] = rv[0];
            g_topi[b * Kk + k] = si[ri[0]];
            sv[ri[0]] = -1e30f;
        }
        __syncthreads();
    }
}

// ---------------- fuse labels + p_sim + combine -----------------------------
__global__ void k_final(const void* __restrict__ y, float* __restrict__ out) {
    __shared__ float fu[8][48];
    int t = threadIdx.x, warp = t >> 5, lane = t & 31;
    int b = blockIdx.x * 8 + warp;
    if (b >= Bb) return;
    fu[warp][lane] = 0.f;
    if (lane < 16) fu[warp][lane + 32] = 0.f;
    __syncwarp();
    if (lane < Kk) {
        float val = g_topv[b * Kk + lane];
        int id = g_topi[b * Kk + lane];
        int cls = load_idx(y, id);
        if ((unsigned)cls < (unsigned)Cc)
            atomicAdd(&fu[warp][cls], expf(val));
    }
    __syncwarp();
    float f0 = fu[warp][lane];
    float f1 = (lane < 15) ? fu[warp][lane + 32] : -1e30f;
    float m = fmaxf(f0, f1);
#pragma unroll
    for (int o = 16; o; o >>= 1) m = fmaxf(m, __shfl_xor_sync(0xffffffffu, m, o));
    float se = expf(f0 - m) + ((lane < 15) ? expf(f1 - m) : 0.f);
#pragma unroll
    for (int o = 16; o; o >>= 1) se += __shfl_xor_sync(0xffffffffu, se, o);
    float lse = m + logf(se);
    out[b * Cc + lane] = 0.5f * g_plc[b * Cc + lane] + 0.5f * (f0 - lse);
    if (lane < 15)
        out[b * Cc + lane + 32] = 0.5f * g_plc[b * Cc + lane + 32] + 0.5f * (f1 - lse);
}

// ---------------- launcher ----------------------------------------------------
extern "C" void kernel_launch(void* const* d_in, const int* in_sizes, int n_in,
                              void* d_out, int out_size) {
    int i = 0;
    const float* x    = (const float*)d_in[i++];      // [N,128]
    const void*  ei   = d_in[i++];                    // [2,E] int32 or int64
    const void*  y    = d_in[i++];                    // [B]   int32 or int64
    if (i < n_in && in_sizes[i] == 1) i++;            // batch_size scalar (skip)
    const float* W1   = (const float*)d_in[i++];
    const float* b1   = (const float*)d_in[i++];
    const float* W2   = (const float*)d_in[i++];
    const float* b2   = (const float*)d_in[i++];
    const float* attl = (const float*)d_in[i++];
    const float* attlb= (const float*)d_in[i++];
    const float* attr = (const float*)d_in[i++];
    const float* attrb= (const float*)d_in[i++];
    float* out = (float*)d_out;

    // dtype probe, then graph structure
    k_detect<<<1, 1>>>(ei);
    k_zero<<<(Nn + 255) / 256, 256>>>();
    k_deg<<<(Ee + 255) / 256, 256>>>(ei);
    k_scan1<<<NBLK, 1024>>>();
    k_scan2<<<1, 128>>>();
    k_scan3<<<(Nn + 255) / 256, 256>>>();
    k_dinv<<<(Nn + 255) / 256, 256>>>();
    k_fill<<<(Ee + 255) / 256, 256>>>(ei);

    // encoder
    k_h0<<<Nn / 32, 256>>>(x, W1, b1);
    for (int l = 0; l < 2; l++) {
        // layer 1 output is only consumed for the first Bb rows (head)
        int nodes = (l == 0) ? Nn : Bb;
        k_alar<<<Nn / 8, 256>>>(l, attl, attlb, attr, attrb);
        k_coef<<<(Ee + 255) / 256, 256>>>(nodes);
        k_gather<<<(nodes + 7) / 8, 256>>>(l, nodes);
        k_finalize<<<(nodes * (Hh / 4)) / 256, 256>>>();
    }

    // head
    int write_emb = (out_size >= Bb * Cc + Bb * Hh) ? 1 : 0;
    k_an<<<Bb / 8, 256>>>(out + (size_t)Bb * Cc, write_emb);
    k_logits<<<Bb / 8, 256>>>(W2, b2);
    dim3 gs(Bb / 128, Bb / 128);
    k_sim<<<gs, 256>>>();
    k_topk<<<Bb, 256>>>();
    k_final<<<Bb / 8, 256>>>(y, out);
}